// round 1
// baseline (speedup 1.0000x reference)
#include <cuda_runtime.h>
#include <math.h>

#define NN 5000
#define NE 80000
#define HD 128
#define NR 64
#define AS 12   // acc stride per (n,h): s1, wx,wy,wz, mxx,mxy,mxz,myy, myz,mzz, pad, pad

#define PI_OVER_CUT 0.6283185307179586f

__device__ __align__(16) float g_ZP[NN * HD];
__device__ __align__(16) float g_ZQ[NN * HD];
__device__ __align__(16) float g_acc[(size_t)NN * HD * AS];
__device__ __align__(16) float g_ln[NN * HD];
__device__ __align__(16) float g_nrm[NN * HD * 3];

__device__ __forceinline__ void red4(float* p, float a, float b, float c, float d) {
    asm volatile("red.global.add.v4.f32 [%0], {%1,%2,%3,%4};"
                 :: "l"(p), "f"(a), "f"(b), "f"(c), "f"(d) : "memory");
}
__device__ __forceinline__ void red2(float* p, float a, float b) {
    asm volatile("red.global.add.v2.f32 [%0], {%1,%2};"
                 :: "l"(p), "f"(a), "f"(b) : "memory");
}
__device__ __forceinline__ float silu_f(float x) { return x / (1.0f + expf(-x)); }

// ---------------- K0: zero the accumulator ----------------
__global__ void k0_zero() {
    size_t n = (size_t)NN * HD * AS / 4;
    float4* p = (float4*)g_acc;
    for (size_t i = blockIdx.x * (size_t)blockDim.x + threadIdx.x; i < n;
         i += (size_t)gridDim.x * blockDim.x)
        p[i] = make_float4(0.f, 0.f, 0.f, 0.f);
}

// ---------------- K1: per-node ZP/ZQ ----------------
// ZP[n,h] = sum_k W_emb2[h,k]     * emb[z[n],k]
// ZQ[n,h] = sum_k W_emb2[h,128+k] * emb[z[n],k]
__global__ void k1_nodepre(const int* __restrict__ z, const float* __restrict__ emb,
                           const float* __restrict__ W_emb2) {
    extern __shared__ float sm[];
    float* sWT = sm;             // [256][129] transposed W_emb2 (padded)
    float* sZ  = sm + 256 * 129; // [128]
    int t = threadIdx.x;
    for (int i = t; i < HD * 2 * HD; i += 128) {
        int hh = i >> 8, k = i & 255;
        sWT[k * 129 + hh] = W_emb2[i];
    }
    for (int n = blockIdx.x; n < NN; n += gridDim.x) {
        __syncthreads();
        sZ[t] = emb[(size_t)z[n] * HD + t];
        __syncthreads();
        float zp = 0.f, zq = 0.f;
#pragma unroll 4
        for (int k = 0; k < HD; k++) {
            float zk = sZ[k];
            zp += sWT[k * 129 + t] * zk;
            zq += sWT[(k + 128) * 129 + t] * zk;
        }
        g_ZP[(size_t)n * HD + t] = zp;
        g_ZQ[(size_t)n * HD + t] = zq;
    }
}

// ---------------- K2: fused edge kernel ----------------
// 512 threads = 4 groups x 128 h-threads, 64 edges per block.
__global__ __launch_bounds__(512) void k2_edge(
    const int* __restrict__ ei, const float* __restrict__ ew,
    const float* __restrict__ evec, const float* __restrict__ eattr,
    const float* __restrict__ b_emb2,
    const float* __restrict__ Wd1, const float* __restrict__ bd1,
    const float* __restrict__ Wd2, const float* __restrict__ bd2,
    const float* __restrict__ Wd3, const float* __restrict__ bd3) {
    extern __shared__ float sm[];
    float* sWdT  = sm;                 // [64 k][385] : 3 mats transposed, padded
    float* sAttr = sm + 64 * 385;      // [64 e][64 k]
    float* sCut  = sAttr + 64 * 64;    // [64]
    float* sVx   = sCut + 64;
    float* sVy   = sVx + 64;
    float* sVz   = sVy + 64;
    int*   sSrc  = (int*)(sVz + 64);
    int*   sDst  = sSrc + 64;

    const int tid = threadIdx.x;
    const int e0  = blockIdx.x * 64;

    for (int i = tid; i < HD * NR; i += 512) {
        int hh = i >> 6, k = i & 63;
        sWdT[k * 385 + hh]       = Wd1[i];
        sWdT[k * 385 + 128 + hh] = Wd2[i];
        sWdT[k * 385 + 256 + hh] = Wd3[i];
    }
    for (int i = tid; i < 64 * NR; i += 512) sAttr[i] = eattr[(size_t)e0 * NR + i];
    if (tid < 64) {
        int e = e0 + tid;
        sSrc[tid] = ei[e];
        sDst[tid] = ei[NE + e];
        float w  = ew[e];
        sCut[tid] = (w < 5.0f) ? 0.5f * (cosf(w * PI_OVER_CUT) + 1.0f) : 0.0f;
        sVx[tid] = evec[3 * e + 0];
        sVy[tid] = evec[3 * e + 1];
        sVz[tid] = evec[3 * e + 2];
    }
    __syncthreads();

    const int h   = tid & 127;
    const int grp = tid >> 7;
    const float bemb = b_emb2[h];
    const float b1 = bd1[h], b2 = bd2[h], b3 = bd3[h];

    for (int eb = 0; eb < 16; eb += 4) {
        int   el[4];
        float C[4], d1[4], d2[4], d3[4];
#pragma unroll
        for (int i = 0; i < 4; i++) {
            el[i] = grp * 16 + eb + i;
            int s = sSrc[el[i]], d = sDst[el[i]];
            C[i] = sCut[el[i]] * (g_ZP[(size_t)s * HD + h] + g_ZQ[(size_t)d * HD + h] + bemb);
            d1[i] = 0.f; d2[i] = 0.f; d3[i] = 0.f;
        }
#pragma unroll 4
        for (int k = 0; k < NR; k++) {
            float w1 = sWdT[k * 385 + h];
            float w2 = sWdT[k * 385 + 128 + h];
            float w3 = sWdT[k * 385 + 256 + h];
#pragma unroll
            for (int i = 0; i < 4; i++) {
                float a = sAttr[el[i] * NR + k];
                d1[i] += w1 * a; d2[i] += w2 * a; d3[i] += w3 * a;
            }
        }
#pragma unroll
        for (int i = 0; i < 4; i++) {
            int e = el[i];
            float f1 = (d1[i] + b1) * C[i];
            float f2 = (d2[i] + b2) * C[i];
            float f3 = (d3[i] + b3) * C[i];
            float vx = sVx[e], vy = sVy[e], vz = sVz[e];
            float* p = &g_acc[((size_t)sSrc[e] * HD + h) * AS];
            red4(p,     f1,             f2 * vx,        f2 * vy,        f2 * vz);
            red4(p + 4, f3 * vx * vx,   f3 * vx * vy,   f3 * vx * vz,   f3 * vy * vy);
            red2(p + 8, f3 * vy * vz,   f3 * vz * vz);
        }
    }
}

// ---------------- K3: tn + LayerNorm ----------------
__global__ void k3_tnln(const float* __restrict__ ln_g, const float* __restrict__ ln_b) {
    __shared__ float sred[4];
    __shared__ float sval;
    int n = blockIdx.x, h = threadIdx.x;
    const float* a = &g_acc[((size_t)n * HD + h) * AS];
    float4 p0 = *(const float4*)a;
    float4 p1 = *(const float4*)(a + 4);
    float2 p2 = *(const float2*)(a + 8);
    float s1 = p0.x, wx = p0.y, wy = p0.z, wz = p0.w;
    float mxx = p1.x, mxy = p1.y, mxz = p1.z, myy = p1.w, myz = p2.x, mzz = p2.y;
    float tr3 = (mxx + myy + mzz) * (1.0f / 3.0f);
    float dxx = s1 + mxx - tr3, dyy = s1 + myy - tr3, dzz = s1 + mzz - tr3;
    float t01 = mxy - wz, t10 = mxy + wz, t02 = mxz + wy;
    float t20 = mxz - wy, t12 = myz - wx, t21 = myz + wx;
    float tn = dxx * dxx + dyy * dyy + dzz * dzz + t01 * t01 + t10 * t10 +
               t02 * t02 + t20 * t20 + t12 * t12 + t21 * t21;

    float v = tn;
#pragma unroll
    for (int o = 16; o; o >>= 1) v += __shfl_xor_sync(0xffffffffu, v, o);
    if ((h & 31) == 0) sred[h >> 5] = v;
    __syncthreads();
    if (h == 0) sval = (sred[0] + sred[1] + sred[2] + sred[3]) * (1.0f / HD);
    __syncthreads();
    float mu = sval;
    float dv = tn - mu;
    v = dv * dv;
#pragma unroll
    for (int o = 16; o; o >>= 1) v += __shfl_xor_sync(0xffffffffu, v, o);
    __syncthreads();
    if ((h & 31) == 0) sred[h >> 5] = v;
    __syncthreads();
    if (h == 0) sval = rsqrtf((sred[0] + sred[1] + sred[2] + sred[3]) * (1.0f / HD) + 1e-5f);
    __syncthreads();
    g_ln[(size_t)n * HD + h] = dv * sval * ln_g[h] + ln_b[h];
}

// ---------------- K4: MLP (8 nodes / block) ----------------
__global__ __launch_bounds__(128) void k4_mlp(
    const float* __restrict__ Ws1, const float* __restrict__ bs1,
    const float* __restrict__ Ws2, const float* __restrict__ bs2) {
    __shared__ float sX[8 * HD];
    __shared__ float sY1[8 * 2 * HD];
    __shared__ float sW[16 * 385];
    int t = threadIdx.x;
    int nb = blockIdx.x * 8;
    for (int i = t; i < 8 * HD; i += 128) sX[i] = g_ln[(size_t)nb * HD + i];
    __syncthreads();

    float acc[8][2];
#pragma unroll
    for (int nl = 0; nl < 8; nl++) { acc[nl][0] = 0.f; acc[nl][1] = 0.f; }
    for (int h0 = 0; h0 < HD; h0 += 16) {
        for (int i = t; i < 256 * 16; i += 128) {
            int j = i >> 4, hh = i & 15;
            sW[hh * 385 + j] = Ws1[j * HD + h0 + hh];
        }
        __syncthreads();
#pragma unroll
        for (int hh = 0; hh < 16; hh++) {
            float w0 = sW[hh * 385 + t], w1 = sW[hh * 385 + 128 + t];
#pragma unroll
            for (int nl = 0; nl < 8; nl++) {
                float x = sX[nl * HD + h0 + hh];
                acc[nl][0] += w0 * x; acc[nl][1] += w1 * x;
            }
        }
        __syncthreads();
    }
    {
        float bb0 = bs1[t], bb1 = bs1[t + 128];
#pragma unroll
        for (int nl = 0; nl < 8; nl++) {
            sY1[nl * 256 + t]       = silu_f(acc[nl][0] + bb0);
            sY1[nl * 256 + 128 + t] = silu_f(acc[nl][1] + bb1);
        }
    }
    __syncthreads();

    float a2[8][3];
#pragma unroll
    for (int nl = 0; nl < 8; nl++) { a2[nl][0] = 0.f; a2[nl][1] = 0.f; a2[nl][2] = 0.f; }
    for (int k0 = 0; k0 < 256; k0 += 16) {
        for (int i = t; i < 384 * 16; i += 128) {
            int j = i >> 4, kk = i & 15;
            sW[kk * 385 + j] = Ws2[j * 256 + k0 + kk];
        }
        __syncthreads();
#pragma unroll
        for (int kk = 0; kk < 16; kk++) {
            float w0 = sW[kk * 385 + t], w1 = sW[kk * 385 + 128 + t], w2 = sW[kk * 385 + 256 + t];
#pragma unroll
            for (int nl = 0; nl < 8; nl++) {
                float x = sY1[nl * 256 + k0 + kk];
                a2[nl][0] += w0 * x; a2[nl][1] += w1 * x; a2[nl][2] += w2 * x;
            }
        }
        __syncthreads();
    }
    float c0 = bs2[t], c1 = bs2[t + 128], c2 = bs2[t + 256];
#pragma unroll
    for (int nl = 0; nl < 8; nl++) {
        size_t base = (size_t)(nb + nl) * 384;
        g_nrm[base + t]       = silu_f(a2[nl][0] + c0);
        g_nrm[base + 128 + t] = silu_f(a2[nl][1] + c1);
        g_nrm[base + 256 + t] = silu_f(a2[nl][2] + c2);
    }
}

// ---------------- K5: Wt transforms + output assembly (4 nodes / block) ----------------
__global__ __launch_bounds__(128) void k5_out(
    const float* __restrict__ Wt1, const float* __restrict__ Wt2,
    const float* __restrict__ Wt3, float* __restrict__ out) {
    extern __shared__ float sm[];
    float* sAcc = sm;                // [4][128][12]
    float* sWt  = sm + 4 * HD * AS;  // [16][389]
    int t  = threadIdx.x;
    int nb = blockIdx.x * 4;
    {
        const float4* src = (const float4*)&g_acc[(size_t)nb * HD * AS];
        float4* dst = (float4*)sAcc;
        for (int i = t; i < 4 * HD * 3; i += 128) dst[i] = src[i];
    }
    __syncthreads();

    float acc[4][10];
#pragma unroll
    for (int nl = 0; nl < 4; nl++)
#pragma unroll
        for (int c = 0; c < 10; c++) acc[nl][c] = 0.f;

    for (int h0 = 0; h0 < HD; h0 += 16) {
        for (int i = t; i < 3 * HD * 16; i += 128) {
            int m = i >> 11;
            int r = i & 2047;
            int g = r >> 4, hh = r & 15;
            const float* W = (m == 0) ? Wt1 : ((m == 1) ? Wt2 : Wt3);
            sWt[hh * 389 + m * 128 + g] = W[g * HD + h0 + hh];
        }
        __syncthreads();
#pragma unroll
        for (int hh = 0; hh < 16; hh++) {
            float w1 = sWt[hh * 389 + t], w2 = sWt[hh * 389 + 128 + t], w3 = sWt[hh * 389 + 256 + t];
#pragma unroll
            for (int nl = 0; nl < 4; nl++) {
                const float* ap = &sAcc[(nl * HD + h0 + hh) * AS];
                float4 p0 = *(const float4*)ap;
                float4 p1 = *(const float4*)(ap + 4);
                float2 p2 = *(const float2*)(ap + 8);
                acc[nl][0] += w1 * p0.x;
                acc[nl][1] += w2 * p0.y; acc[nl][2] += w2 * p0.z; acc[nl][3] += w2 * p0.w;
                acc[nl][4] += w3 * p1.x; acc[nl][5] += w3 * p1.y; acc[nl][6] += w3 * p1.z;
                acc[nl][7] += w3 * p1.w; acc[nl][8] += w3 * p2.x; acc[nl][9] += w3 * p2.y;
            }
        }
        __syncthreads();
    }

#pragma unroll
    for (int nl = 0; nl < 4; nl++) {
        int n = nb + nl;
        float n0 = g_nrm[(size_t)n * 384 + t * 3 + 0];
        float n1 = g_nrm[(size_t)n * 384 + t * 3 + 1];
        float n2 = g_nrm[(size_t)n * 384 + t * 3 + 2];
        float s1 = acc[nl][0], wx = acc[nl][1], wy = acc[nl][2], wz = acc[nl][3];
        float mxx = acc[nl][4], mxy = acc[nl][5], mxz = acc[nl][6];
        float myy = acc[nl][7], myz = acc[nl][8], mzz = acc[nl][9];
        float tr3 = (mxx + myy + mzz) * (1.0f / 3.0f);
        float dI = n0 * s1;
        float* o = out + ((size_t)n * HD + t) * 9;
        o[0] = dI + n2 * (mxx - tr3);
        o[1] = -n1 * wz + n2 * mxy;
        o[2] =  n1 * wy + n2 * mxz;
        o[3] =  n1 * wz + n2 * mxy;
        o[4] = dI + n2 * (myy - tr3);
        o[5] = -n1 * wx + n2 * myz;
        o[6] = -n1 * wy + n2 * mxz;
        o[7] =  n1 * wx + n2 * myz;
        o[8] = dI + n2 * (mzz - tr3);
    }
}

#define K1_SMEM ((256 * 129 + 128) * 4)
#define K2_SMEM ((64 * 385 + 64 * 64 + 4 * 64) * 4 + 2 * 64 * 4)
#define K5_SMEM ((4 * HD * AS + 16 * 389) * 4)

extern "C" void kernel_launch(void* const* d_in, const int* in_sizes, int n_in,
                              void* d_out, int out_size) {
    (void)in_sizes; (void)n_in; (void)out_size;
    const int*   z      = (const int*)d_in[0];
    const int*   ei     = (const int*)d_in[1];
    const float* ew     = (const float*)d_in[2];
    const float* evec   = (const float*)d_in[3];
    const float* eattr  = (const float*)d_in[4];
    const float* emb    = (const float*)d_in[5];
    const float* W_emb2 = (const float*)d_in[6];
    const float* b_emb2 = (const float*)d_in[7];
    const float* Wd1 = (const float*)d_in[8],  *bd1 = (const float*)d_in[9];
    const float* Wd2 = (const float*)d_in[10], *bd2 = (const float*)d_in[11];
    const float* Wd3 = (const float*)d_in[12], *bd3 = (const float*)d_in[13];
    const float* Wt1 = (const float*)d_in[14], *Wt2 = (const float*)d_in[15];
    const float* Wt3 = (const float*)d_in[16];
    const float* Ws1 = (const float*)d_in[17], *bs1 = (const float*)d_in[18];
    const float* Ws2 = (const float*)d_in[19], *bs2 = (const float*)d_in[20];
    const float* ln_g = (const float*)d_in[21], *ln_b = (const float*)d_in[22];
    float* out = (float*)d_out;

    cudaFuncSetAttribute(k1_nodepre, cudaFuncAttributeMaxDynamicSharedMemorySize, K1_SMEM);
    cudaFuncSetAttribute(k2_edge,    cudaFuncAttributeMaxDynamicSharedMemorySize, K2_SMEM);
    cudaFuncSetAttribute(k5_out,     cudaFuncAttributeMaxDynamicSharedMemorySize, K5_SMEM);

    k0_zero<<<512, 256>>>();
    k1_nodepre<<<160, 128, K1_SMEM>>>(z, emb, W_emb2);
    k2_edge<<<NE / 64, 512, K2_SMEM>>>(ei, ew, evec, eattr, b_emb2,
                                       Wd1, bd1, Wd2, bd2, Wd3, bd3);
    k3_tnln<<<NN, 128>>>(ln_g, ln_b);
    k4_mlp<<<NN / 8, 128>>>(Ws1, bs1, Ws2, bs2);
    k5_out<<<NN / 4, 128, K5_SMEM>>>(Wt1, Wt2, Wt3, out);
}

// round 2
// speedup vs baseline: 1.0929x; 1.0929x over previous
#include <cuda_runtime.h>
#include <math.h>

#define NN 5000
#define NE 80000
#define HD 128
#define NR 64
#define AS 12   // acc stride per (n,h): s1, wx,wy,wz, mxx,mxy,mxz,myy, myz,mzz, pad, pad

#define PI_OVER_CUT 0.6283185307179586f

typedef unsigned long long ull;

__device__ __align__(16) float g_ZP[NN * HD];
__device__ __align__(16) float g_ZQ[NN * HD];
__device__ __align__(16) float g_acc[(size_t)NN * HD * AS];
__device__ __align__(16) float g_ln[NN * HD];
__device__ __align__(16) float g_nrm[NN * HD * 3];
__device__ int g_hist[NN];
__device__ int g_cur[NN];
__device__ int g_perm[NE];

__device__ __forceinline__ void red4(float* p, float a, float b, float c, float d) {
    asm volatile("red.global.add.v4.f32 [%0], {%1,%2,%3,%4};"
                 :: "l"(p), "f"(a), "f"(b), "f"(c), "f"(d) : "memory");
}
__device__ __forceinline__ void red2(float* p, float a, float b) {
    asm volatile("red.global.add.v2.f32 [%0], {%1,%2};"
                 :: "l"(p), "f"(a), "f"(b) : "memory");
}
__device__ __forceinline__ ull pk2(float a, float b) {
    ull r;
    asm("mov.b64 %0, {%1,%2};" : "=l"(r) : "f"(a), "f"(b));
    return r;
}
__device__ __forceinline__ void unpk2(ull v, float& a, float& b) {
    asm("mov.b64 {%0,%1}, %2;" : "=f"(a), "=f"(b) : "l"(v));
}
__device__ __forceinline__ ull fma2(ull a, ull b, ull c) {
    ull d;
    asm("fma.rn.f32x2 %0, %1, %2, %3;" : "=l"(d) : "l"(a), "l"(b), "l"(c));
    return d;
}
__device__ __forceinline__ float silu_f(float x) { return x / (1.0f + expf(-x)); }

// ---------------- K0: zero accumulator + histogram ----------------
__global__ void k0_zero() {
    size_t n = (size_t)NN * HD * AS / 4;
    float4* p = (float4*)g_acc;
    for (size_t i = blockIdx.x * (size_t)blockDim.x + threadIdx.x; i < n;
         i += (size_t)gridDim.x * blockDim.x)
        p[i] = make_float4(0.f, 0.f, 0.f, 0.f);
    for (int i = blockIdx.x * blockDim.x + threadIdx.x; i < NN;
         i += gridDim.x * blockDim.x)
        g_hist[i] = 0;
}

// ---------------- K1: per-node ZP/ZQ ----------------
__global__ void k1_nodepre(const int* __restrict__ z, const float* __restrict__ emb,
                           const float* __restrict__ W_emb2) {
    extern __shared__ float sm[];
    float* sWT = sm;             // [256][129] transposed W_emb2 (padded)
    float* sZ  = sm + 256 * 129; // [128]
    int t = threadIdx.x;
    for (int i = t; i < HD * 2 * HD; i += 128) {
        int hh = i >> 8, k = i & 255;
        sWT[k * 129 + hh] = W_emb2[i];
    }
    for (int n = blockIdx.x; n < NN; n += gridDim.x) {
        __syncthreads();
        sZ[t] = emb[(size_t)z[n] * HD + t];
        __syncthreads();
        float zp = 0.f, zq = 0.f;
#pragma unroll 4
        for (int k = 0; k < HD; k++) {
            float zk = sZ[k];
            zp += sWT[k * 129 + t] * zk;
            zq += sWT[(k + 128) * 129 + t] * zk;
        }
        g_ZP[(size_t)n * HD + t] = zp;
        g_ZQ[(size_t)n * HD + t] = zq;
    }
}

// ---------------- sort: histogram ----------------
__global__ void kh_hist(const int* __restrict__ ei) {
    int e = blockIdx.x * blockDim.x + threadIdx.x;
    if (e < NE) atomicAdd(&g_hist[ei[e]], 1);
}

// ---------------- sort: exclusive scan (1 block, 1024 thr) ----------------
__global__ void ks_scan() {
    __shared__ int wsum[32];
    __shared__ int carry;
    int t = threadIdx.x, lane = t & 31, wid = t >> 5;
    if (t == 0) carry = 0;
    __syncthreads();
    for (int c = 0; c < 5; c++) {
        int idx = c * 1024 + t;
        int v = (idx < NN) ? g_hist[idx] : 0;
        int x = v;
#pragma unroll
        for (int o = 1; o < 32; o <<= 1) {
            int y = __shfl_up_sync(0xffffffffu, x, o);
            if (lane >= o) x += y;
        }
        if (lane == 31) wsum[wid] = x;
        __syncthreads();
        if (wid == 0) {
            int s = wsum[lane];
#pragma unroll
            for (int o = 1; o < 32; o <<= 1) {
                int y = __shfl_up_sync(0xffffffffu, s, o);
                if (lane >= o) s += y;
            }
            wsum[lane] = s;
        }
        __syncthreads();
        int pref = carry + (wid ? wsum[wid - 1] : 0) + x - v;
        if (idx < NN) g_cur[idx] = pref;
        __syncthreads();
        if (t == 0) carry += wsum[31];
        __syncthreads();
    }
}

// ---------------- sort: scatter ----------------
__global__ void ks_scatter(const int* __restrict__ ei) {
    int e = blockIdx.x * blockDim.x + threadIdx.x;
    if (e < NE) {
        int s = ei[e];
        int p = atomicAdd(&g_cur[s], 1);
        g_perm[p] = e;
    }
}

// ---------------- K2: fused edge kernel (sorted, f32x2, reg-aggregated) ----------------
// 512 threads = 4 groups x 128 h-threads, 64 sorted edges per block.
__global__ __launch_bounds__(512) void k2_edge(
    const int* __restrict__ ei, const float* __restrict__ ew,
    const float* __restrict__ evec, const float* __restrict__ eattr,
    const float* __restrict__ b_emb2,
    const float* __restrict__ Wd1, const float* __restrict__ bd1,
    const float* __restrict__ Wd2, const float* __restrict__ bd2,
    const float* __restrict__ Wd3, const float* __restrict__ bd3,
    int e0base) {
    extern __shared__ float sm[];
    float* sWdT   = sm;                  // [64 k][385] : 3 mats transposed, padded
    float* sAttrT = sm + 64 * 385;       // [64 k][64 e] (k-major!)
    float* sCut   = sAttrT + 64 * 64;    // [64]
    float* sVx    = sCut + 64;
    float* sVy    = sVx + 64;
    float* sVz    = sVy + 64;
    int*   sSrc   = (int*)(sVz + 64);
    int*   sDst   = sSrc + 64;

    const int tid = threadIdx.x;
    const int e0  = e0base + blockIdx.x * 64;

    for (int i = tid; i < HD * NR; i += 512) {
        int hh = i >> 6, k = i & 63;
        sWdT[k * 385 + hh]       = Wd1[i];
        sWdT[k * 385 + 128 + hh] = Wd2[i];
        sWdT[k * 385 + 256 + hh] = Wd3[i];
    }
    if (tid < 64) {
        int pe = g_perm[e0 + tid];
        sSrc[tid] = ei[pe];
        sDst[tid] = ei[NE + pe];
        float w = ew[pe];
        sCut[tid] = (w < 5.0f) ? 0.5f * (cosf(w * PI_OVER_CUT) + 1.0f) : 0.0f;
        sVx[tid] = evec[3 * pe + 0];
        sVy[tid] = evec[3 * pe + 1];
        sVz[tid] = evec[3 * pe + 2];
    }
    // attr tile, transposed to k-major
    {
        int e = tid & 63, kq = tid >> 6;  // kq in 0..7
        int pe = g_perm[e0 + e];
        const float4* arow = (const float4*)(eattr + (size_t)pe * NR);
        float4 a0 = arow[kq * 2], a1 = arow[kq * 2 + 1];
        int kk = kq * 8;
        sAttrT[(kk + 0) * 64 + e] = a0.x;
        sAttrT[(kk + 1) * 64 + e] = a0.y;
        sAttrT[(kk + 2) * 64 + e] = a0.z;
        sAttrT[(kk + 3) * 64 + e] = a0.w;
        sAttrT[(kk + 4) * 64 + e] = a1.x;
        sAttrT[(kk + 5) * 64 + e] = a1.y;
        sAttrT[(kk + 6) * 64 + e] = a1.z;
        sAttrT[(kk + 7) * 64 + e] = a1.w;
    }
    __syncthreads();

    const int h   = tid & 127;
    const int grp = tid >> 7;
    const float bemb = b_emb2[h];
    const float b1 = bd1[h], b2 = bd2[h], b3 = bd3[h];

    float racc[10];
#pragma unroll
    for (int c = 0; c < 10; c++) racc[c] = 0.f;
    int cur = sSrc[grp * 16];

#define FLUSH()                                                                 \
    do {                                                                        \
        float* p_ = &g_acc[((size_t)cur * HD + h) * AS];                        \
        red4(p_, racc[0], racc[1], racc[2], racc[3]);                           \
        red4(p_ + 4, racc[4], racc[5], racc[6], racc[7]);                       \
        red2(p_ + 8, racc[8], racc[9]);                                         \
    } while (0)

    for (int chunk = 0; chunk < 2; chunk++) {
        int base = grp * 16 + chunk * 8;
        float C[8];
#pragma unroll
        for (int i = 0; i < 8; i++) {
            int e = base + i;
            C[i] = sCut[e] *
                   (g_ZP[(size_t)sSrc[e] * HD + h] + g_ZQ[(size_t)sDst[e] * HD + h] + bemb);
        }
        ull d[4][3];
#pragma unroll
        for (int p = 0; p < 4; p++) { d[p][0] = 0ull; d[p][1] = 0ull; d[p][2] = 0ull; }

#pragma unroll 4
        for (int k = 0; k < NR; k++) {
            float w1 = sWdT[k * 385 + h];
            float w2 = sWdT[k * 385 + 128 + h];
            float w3 = sWdT[k * 385 + 256 + h];
            ull pw1 = pk2(w1, w1), pw2 = pk2(w2, w2), pw3 = pk2(w3, w3);
            const ull* ar = (const ull*)(sAttrT + k * 64 + base);
#pragma unroll
            for (int p = 0; p < 4; p++) {
                ull a = ar[p];
                d[p][0] = fma2(pw1, a, d[p][0]);
                d[p][1] = fma2(pw2, a, d[p][1]);
                d[p][2] = fma2(pw3, a, d[p][2]);
            }
        }

#pragma unroll
        for (int p = 0; p < 4; p++) {
            float d1a, d1b, d2a, d2b, d3a, d3b;
            unpk2(d[p][0], d1a, d1b);
            unpk2(d[p][1], d2a, d2b);
            unpk2(d[p][2], d3a, d3b);
#pragma unroll
            for (int half = 0; half < 2; half++) {
                int e = base + 2 * p + half;
                float dd1 = half ? d1b : d1a;
                float dd2 = half ? d2b : d2a;
                float dd3 = half ? d3b : d3a;
                float Ci = C[2 * p + half];
                float f1 = (dd1 + b1) * Ci;
                float f2 = (dd2 + b2) * Ci;
                float f3 = (dd3 + b3) * Ci;
                int s = sSrc[e];
                if (s != cur) {
                    FLUSH();
#pragma unroll
                    for (int c = 0; c < 10; c++) racc[c] = 0.f;
                    cur = s;
                }
                float vx = sVx[e], vy = sVy[e], vz = sVz[e];
                racc[0] += f1;
                racc[1] += f2 * vx; racc[2] += f2 * vy; racc[3] += f2 * vz;
                float f3x = f3 * vx, f3y = f3 * vy, f3z = f3 * vz;
                racc[4] += f3x * vx; racc[5] += f3x * vy; racc[6] += f3x * vz;
                racc[7] += f3y * vy; racc[8] += f3y * vz; racc[9] += f3z * vz;
            }
        }
    }
    FLUSH();
#undef FLUSH
}

// ---------------- K3: tn + LayerNorm ----------------
__global__ void k3_tnln(const float* __restrict__ ln_g, const float* __restrict__ ln_b) {
    __shared__ float sred[4];
    __shared__ float sval;
    int n = blockIdx.x, h = threadIdx.x;
    const float* a = &g_acc[((size_t)n * HD + h) * AS];
    float4 p0 = *(const float4*)a;
    float4 p1 = *(const float4*)(a + 4);
    float2 p2 = *(const float2*)(a + 8);
    float s1 = p0.x, wx = p0.y, wy = p0.z, wz = p0.w;
    float mxx = p1.x, mxy = p1.y, mxz = p1.z, myy = p1.w, myz = p2.x, mzz = p2.y;
    float tr3 = (mxx + myy + mzz) * (1.0f / 3.0f);
    float dxx = s1 + mxx - tr3, dyy = s1 + myy - tr3, dzz = s1 + mzz - tr3;
    float t01 = mxy - wz, t10 = mxy + wz, t02 = mxz + wy;
    float t20 = mxz - wy, t12 = myz - wx, t21 = myz + wx;
    float tn = dxx * dxx + dyy * dyy + dzz * dzz + t01 * t01 + t10 * t10 +
               t02 * t02 + t20 * t20 + t12 * t12 + t21 * t21;

    float v = tn;
#pragma unroll
    for (int o = 16; o; o >>= 1) v += __shfl_xor_sync(0xffffffffu, v, o);
    if ((h & 31) == 0) sred[h >> 5] = v;
    __syncthreads();
    if (h == 0) sval = (sred[0] + sred[1] + sred[2] + sred[3]) * (1.0f / HD);
    __syncthreads();
    float mu = sval;
    float dv = tn - mu;
    v = dv * dv;
#pragma unroll
    for (int o = 16; o; o >>= 1) v += __shfl_xor_sync(0xffffffffu, v, o);
    __syncthreads();
    if ((h & 31) == 0) sred[h >> 5] = v;
    __syncthreads();
    if (h == 0) sval = rsqrtf((sred[0] + sred[1] + sred[2] + sred[3]) * (1.0f / HD) + 1e-5f);
    __syncthreads();
    g_ln[(size_t)n * HD + h] = dv * sval * ln_g[h] + ln_b[h];
}

// ---------------- K4: MLP (8 nodes / block) ----------------
__global__ __launch_bounds__(128) void k4_mlp(
    const float* __restrict__ Ws1, const float* __restrict__ bs1,
    const float* __restrict__ Ws2, const float* __restrict__ bs2) {
    __shared__ float sX[8 * HD];
    __shared__ float sY1[8 * 2 * HD];
    __shared__ float sW[16 * 385];
    int t = threadIdx.x;
    int nb = blockIdx.x * 8;
    for (int i = t; i < 8 * HD; i += 128) sX[i] = g_ln[(size_t)nb * HD + i];
    __syncthreads();

    float acc[8][2];
#pragma unroll
    for (int nl = 0; nl < 8; nl++) { acc[nl][0] = 0.f; acc[nl][1] = 0.f; }
    for (int h0 = 0; h0 < HD; h0 += 16) {
        for (int i = t; i < 256 * 16; i += 128) {
            int j = i >> 4, hh = i & 15;
            sW[hh * 385 + j] = Ws1[j * HD + h0 + hh];
        }
        __syncthreads();
#pragma unroll
        for (int hh = 0; hh < 16; hh++) {
            float w0 = sW[hh * 385 + t], w1 = sW[hh * 385 + 128 + t];
#pragma unroll
            for (int nl = 0; nl < 8; nl++) {
                float x = sX[nl * HD + h0 + hh];
                acc[nl][0] += w0 * x; acc[nl][1] += w1 * x;
            }
        }
        __syncthreads();
    }
    {
        float bb0 = bs1[t], bb1 = bs1[t + 128];
#pragma unroll
        for (int nl = 0; nl < 8; nl++) {
            sY1[nl * 256 + t]       = silu_f(acc[nl][0] + bb0);
            sY1[nl * 256 + 128 + t] = silu_f(acc[nl][1] + bb1);
        }
    }
    __syncthreads();

    float a2[8][3];
#pragma unroll
    for (int nl = 0; nl < 8; nl++) { a2[nl][0] = 0.f; a2[nl][1] = 0.f; a2[nl][2] = 0.f; }
    for (int k0 = 0; k0 < 256; k0 += 16) {
        for (int i = t; i < 384 * 16; i += 128) {
            int j = i >> 4, kk = i & 15;
            sW[kk * 385 + j] = Ws2[j * 256 + k0 + kk];
        }
        __syncthreads();
#pragma unroll
        for (int kk = 0; kk < 16; kk++) {
            float w0 = sW[kk * 385 + t], w1 = sW[kk * 385 + 128 + t], w2 = sW[kk * 385 + 256 + t];
#pragma unroll
            for (int nl = 0; nl < 8; nl++) {
                float x = sY1[nl * 256 + k0 + kk];
                a2[nl][0] += w0 * x; a2[nl][1] += w1 * x; a2[nl][2] += w2 * x;
            }
        }
        __syncthreads();
    }
    float c0 = bs2[t], c1 = bs2[t + 128], c2 = bs2[t + 256];
#pragma unroll
    for (int nl = 0; nl < 8; nl++) {
        size_t base = (size_t)(nb + nl) * 384;
        g_nrm[base + t]       = silu_f(a2[nl][0] + c0);
        g_nrm[base + 128 + t] = silu_f(a2[nl][1] + c1);
        g_nrm[base + 256 + t] = silu_f(a2[nl][2] + c2);
    }
}

// ---------------- K5: Wt transforms + output assembly (4 nodes / block) ----------------
__global__ __launch_bounds__(128) void k5_out(
    const float* __restrict__ Wt1, const float* __restrict__ Wt2,
    const float* __restrict__ Wt3, float* __restrict__ out) {
    extern __shared__ float sm[];
    float* sAcc = sm;                // [4][128][12]
    float* sWt  = sm + 4 * HD * AS;  // [16][389]
    int t  = threadIdx.x;
    int nb = blockIdx.x * 4;
    {
        const float4* src = (const float4*)&g_acc[(size_t)nb * HD * AS];
        float4* dst = (float4*)sAcc;
        for (int i = t; i < 4 * HD * 3; i += 128) dst[i] = src[i];
    }
    __syncthreads();

    float acc[4][10];
#pragma unroll
    for (int nl = 0; nl < 4; nl++)
#pragma unroll
        for (int c = 0; c < 10; c++) acc[nl][c] = 0.f;

    for (int h0 = 0; h0 < HD; h0 += 16) {
        for (int i = t; i < 3 * HD * 16; i += 128) {
            int m = i >> 11;
            int r = i & 2047;
            int g = r >> 4, hh = r & 15;
            const float* W = (m == 0) ? Wt1 : ((m == 1) ? Wt2 : Wt3);
            sWt[hh * 389 + m * 128 + g] = W[g * HD + h0 + hh];
        }
        __syncthreads();
#pragma unroll
        for (int hh = 0; hh < 16; hh++) {
            float w1 = sWt[hh * 389 + t], w2 = sWt[hh * 389 + 128 + t], w3 = sWt[hh * 389 + 256 + t];
#pragma unroll
            for (int nl = 0; nl < 4; nl++) {
                const float* ap = &sAcc[(nl * HD + h0 + hh) * AS];
                float4 p0 = *(const float4*)ap;
                float4 p1 = *(const float4*)(ap + 4);
                float2 p2 = *(const float2*)(ap + 8);
                acc[nl][0] += w1 * p0.x;
                acc[nl][1] += w2 * p0.y; acc[nl][2] += w2 * p0.z; acc[nl][3] += w2 * p0.w;
                acc[nl][4] += w3 * p1.x; acc[nl][5] += w3 * p1.y; acc[nl][6] += w3 * p1.z;
                acc[nl][7] += w3 * p1.w; acc[nl][8] += w3 * p2.x; acc[nl][9] += w3 * p2.y;
            }
        }
        __syncthreads();
    }

#pragma unroll
    for (int nl = 0; nl < 4; nl++) {
        int n = nb + nl;
        float n0 = g_nrm[(size_t)n * 384 + t * 3 + 0];
        float n1 = g_nrm[(size_t)n * 384 + t * 3 + 1];
        float n2 = g_nrm[(size_t)n * 384 + t * 3 + 2];
        float s1 = acc[nl][0], wx = acc[nl][1], wy = acc[nl][2], wz = acc[nl][3];
        float mxx = acc[nl][4], mxy = acc[nl][5], mxz = acc[nl][6];
        float myy = acc[nl][7], myz = acc[nl][8], mzz = acc[nl][9];
        float tr3 = (mxx + myy + mzz) * (1.0f / 3.0f);
        float dI = n0 * s1;
        float* o = out + ((size_t)n * HD + t) * 9;
        o[0] = dI + n2 * (mxx - tr3);
        o[1] = -n1 * wz + n2 * mxy;
        o[2] =  n1 * wy + n2 * mxz;
        o[3] =  n1 * wz + n2 * mxy;
        o[4] = dI + n2 * (myy - tr3);
        o[5] = -n1 * wx + n2 * myz;
        o[6] = -n1 * wy + n2 * mxz;
        o[7] =  n1 * wx + n2 * myz;
        o[8] = dI + n2 * (mzz - tr3);
    }
}

#define K1_SMEM ((256 * 129 + 128) * 4)
#define K2_SMEM ((64 * 385 + 64 * 64 + 4 * 64) * 4 + 2 * 64 * 4)
#define K5_SMEM ((4 * HD * AS + 16 * 389) * 4)

extern "C" void kernel_launch(void* const* d_in, const int* in_sizes, int n_in,
                              void* d_out, int out_size) {
    (void)in_sizes; (void)n_in; (void)out_size;
    const int*   z      = (const int*)d_in[0];
    const int*   ei     = (const int*)d_in[1];
    const float* ew     = (const float*)d_in[2];
    const float* evec   = (const float*)d_in[3];
    const float* eattr  = (const float*)d_in[4];
    const float* emb    = (const float*)d_in[5];
    const float* W_emb2 = (const float*)d_in[6];
    const float* b_emb2 = (const float*)d_in[7];
    const float* Wd1 = (const float*)d_in[8],  *bd1 = (const float*)d_in[9];
    const float* Wd2 = (const float*)d_in[10], *bd2 = (const float*)d_in[11];
    const float* Wd3 = (const float*)d_in[12], *bd3 = (const float*)d_in[13];
    const float* Wt1 = (const float*)d_in[14], *Wt2 = (const float*)d_in[15];
    const float* Wt3 = (const float*)d_in[16];
    const float* Ws1 = (const float*)d_in[17], *bs1 = (const float*)d_in[18];
    const float* Ws2 = (const float*)d_in[19], *bs2 = (const float*)d_in[20];
    const float* ln_g = (const float*)d_in[21], *ln_b = (const float*)d_in[22];
    float* out = (float*)d_out;

    cudaFuncSetAttribute(k1_nodepre, cudaFuncAttributeMaxDynamicSharedMemorySize, K1_SMEM);
    cudaFuncSetAttribute(k2_edge,    cudaFuncAttributeMaxDynamicSharedMemorySize, K2_SMEM);
    cudaFuncSetAttribute(k5_out,     cudaFuncAttributeMaxDynamicSharedMemorySize, K5_SMEM);

    k0_zero<<<512, 256>>>();
    k1_nodepre<<<160, 128, K1_SMEM>>>(z, emb, W_emb2);
    kh_hist<<<(NE + 511) / 512, 512>>>(ei);
    ks_scan<<<1, 1024>>>();
    ks_scatter<<<(NE + 511) / 512, 512>>>(ei);
    k2_edge<<<625, 512, K2_SMEM>>>(ei, ew, evec, eattr, b_emb2,
                                   Wd1, bd1, Wd2, bd2, Wd3, bd3, 0);
    k2_edge<<<625, 512, K2_SMEM>>>(ei, ew, evec, eattr, b_emb2,
                                   Wd1, bd1, Wd2, bd2, Wd3, bd3, 40000);
    k3_tnln<<<NN, 128>>>(ln_g, ln_b);
    k4_mlp<<<NN / 8, 128>>>(Ws1, bs1, Ws2, bs2);
    k5_out<<<NN / 4, 128, K5_SMEM>>>(Wt1, Wt2, Wt3, out);
}